// round 9
// baseline (speedup 1.0000x reference)
#include <cuda_runtime.h>
#include <cuda_bf16.h>

// video [B=8, C=3, T=32, H=224, W=224] fp32.
// out[b,c,t,y,x] = clip01( clamped-bilinear sample of frame (b,c,t) at
//   src = (coord + shake + 0.5) * (224/240) - 0.5 )
// (trilinear resize 224->240 has identity T axis; jax boundary weight
//  renormalization for the linear kernel == coordinate clamping.)
//
// R8: two-tile software pipeline per block (overlap gather with epilogue).
//  Block = one plane x 32 rows = tiles A (rows yb..yb+15) and B (+16..+31).
//  P1: gather+hlerp A -> hrowA. sync.
//  P2: 4 chunks of { gather 4 rows of B -> hrowB  |  epilogue quad of A }.
//      Tile B's LDG latency hides under tile A's LDS/STG work, so the SM
//      never stops issuing DRAM loads (R6's phase bubble removed).
//  P3: sync, epilogue B.
//  smem 28.7 KB -> 7 blocks/SM; __launch_bounds__(224,7) caps regs at 40.

#define HH 224
#define WW 224
#define TT 32
#define NPLANES 768
#define TILE_Y 16
#define PAIRS_PER_PLANE 7        // 224 / 32
#define THREADS 224
#define SCALE_F (14.0f / 15.0f)

__global__ __launch_bounds__(THREADS, 7) void shake_bilinear_pipe_kernel(
    const float* __restrict__ vid,
    const int*   __restrict__ sh,
    const int*   __restrict__ sw,
    float*       __restrict__ out)
{
    __shared__ float hrowA[TILE_Y][WW];  // 14336 B
    __shared__ float hrowB[TILE_Y][WW];  // 14336 B

    int blk  = blockIdx.x;
    int pair = blk % PAIRS_PER_PLANE;
    int p    = blk / PAIRS_PER_PLANE;    // plane = (b*C + c)*T + t
    int t    = p & (TT - 1);
    int sht  = __ldg(sh + t);
    int swt  = __ldg(sw + t);
    int ybA  = pair * 32;
    int ybB  = ybA + TILE_Y;
    int tid  = threadIdx.x;

    const float* plane = vid + (long long)p * (HH * WW);

    // Horizontal weights: one x column per thread, shared by both tiles.
    int   x   = tid;                     // 0..223
    float sx  = ((float)(x + swt) + 0.5f) * SCALE_F - 0.5f;
    float fh0 = floorf(sx);
    float fx  = sx - fh0;
    int   x0  = (int)fh0;
    int   x0c = max(x0, 0);
    int   x1c = min(x0 + 1, WW - 1);

    // Base source rows per tile (baseA may be -1 at the top edge).
    float syA  = ((float)(ybA + sht) + 0.5f) * SCALE_F - 0.5f;
    int   baseA = (int)floorf(syA);
    float syB  = ((float)(ybB + sht) + 0.5f) * SCALE_F - 0.5f;
    int   baseB = (int)floorf(syB);

    // Epilogue geometry (fixed per thread).
    int x4 = tid % (WW / 4);             // 0..55
    int yy = tid / (WW / 4);             // 0..3
    int xb = x4 * 4;
    float4* outp = (float4*)(out + (long long)p * (HH * WW));

    // ---- Phase 1: gather + hlerp tile A ----
#pragma unroll
    for (int r = 0; r < TILE_Y; r++) {
        int srcr = min(max(baseA + r, 0), HH - 1);
        const float* row = plane + srcr * WW;
        float s0 = __ldg(row + x0c);
        float s1 = __ldg(row + x1c);
        hrowA[r][x] = fmaf(fx, s1 - s0, s0);
    }
    __syncthreads();

    // ---- Phase 2: gather tile B interleaved with epilogue tile A ----
#pragma unroll
    for (int c = 0; c < 4; c++) {
        // gather 4 rows of tile B (8 independent LDGs issued up front)
        float s0[4], s1[4];
#pragma unroll
        for (int r4 = 0; r4 < 4; r4++) {
            int r    = c * 4 + r4;
            int srcr = min(max(baseB + r, 0), HH - 1);
            const float* row = plane + srcr * WW;
            s0[r4] = __ldg(row + x0c);
            s1[r4] = __ldg(row + x1c);
        }

        // epilogue quad of tile A (fills the LDG stall shadow)
        {
            int   y   = yy + 4 * c;      // 0..15
            float sy  = ((float)(ybA + y + sht) + 0.5f) * SCALE_F - 0.5f;
            float f0  = floorf(sy);
            float fy  = sy - f0;
            int   r0  = (int)f0 - baseA; // in [0,14]

            float4 a = *(const float4*)(&hrowA[r0][xb]);
            float4 b = *(const float4*)(&hrowA[r0 + 1][xb]);
            float4 res;
            res.x = fminf(fmaxf(fmaf(fy, b.x - a.x, a.x), 0.0f), 1.0f);
            res.y = fminf(fmaxf(fmaf(fy, b.y - a.y, a.y), 0.0f), 1.0f);
            res.z = fminf(fmaxf(fmaf(fy, b.z - a.z, a.z), 0.0f), 1.0f);
            res.w = fminf(fmaxf(fmaf(fy, b.w - a.w, a.w), 0.0f), 1.0f);
            outp[(ybA + y) * (WW / 4) + x4] = res;
        }

        // complete tile B rows for this chunk
#pragma unroll
        for (int r4 = 0; r4 < 4; r4++) {
            int r = c * 4 + r4;
            hrowB[r][x] = fmaf(fx, s1[r4] - s0[r4], s0[r4]);
        }
    }
    __syncthreads();

    // ---- Phase 3: epilogue tile B ----
#pragma unroll
    for (int k = 0; k < 4; k++) {
        int   y   = yy + 4 * k;
        float sy  = ((float)(ybB + y + sht) + 0.5f) * SCALE_F - 0.5f;
        float f0  = floorf(sy);
        float fy  = sy - f0;
        int   r0  = (int)f0 - baseB;     // in [0,14]

        float4 a = *(const float4*)(&hrowB[r0][xb]);
        float4 b = *(const float4*)(&hrowB[r0 + 1][xb]);
        float4 res;
        res.x = fminf(fmaxf(fmaf(fy, b.x - a.x, a.x), 0.0f), 1.0f);
        res.y = fminf(fmaxf(fmaf(fy, b.y - a.y, a.y), 0.0f), 1.0f);
        res.z = fminf(fmaxf(fmaf(fy, b.z - a.z, a.z), 0.0f), 1.0f);
        res.w = fminf(fmaxf(fmaf(fy, b.w - a.w, a.w), 0.0f), 1.0f);
        outp[(ybB + y) * (WW / 4) + x4] = res;
    }
}

extern "C" void kernel_launch(void* const* d_in, const int* in_sizes, int n_in,
                              void* d_out, int out_size)
{
    const float* vid = (const float*)d_in[0];
    const int*   sh  = (const int*)d_in[1];
    const int*   sw  = (const int*)d_in[2];
    float*       out = (float*)d_out;

    int blocks = NPLANES * PAIRS_PER_PLANE; // 768*7 = 5376
    shake_bilinear_pipe_kernel<<<blocks, THREADS>>>(vid, sh, sw, out);
}

// round 10
// speedup vs baseline: 1.2284x; 1.2284x over previous
#include <cuda_runtime.h>
#include <cuda_bf16.h>

// video [B=8, C=3, T=32, H=224, W=224] fp32.
// out[b,c,t,y,x] = clip01( clamped-bilinear sample of frame (b,c,t) at
//   src = (coord + shake + 0.5) * (224/240) - 0.5 )
// (trilinear resize 224->240 has identity T axis; jax boundary weight
//  renormalization for the linear kernel == coordinate clamping.)
//
// R9: R6 skeleton + shuffle-based gather.
//  A warp's 32 output columns tap a <=31-wide source window, so per row:
//  ONE coalesced LDG.32 per lane (v = row[clamp(baseX+lane)]) and the two
//  bilinear taps come from __shfl_sync(v, i0/i1). Halves gather LDG count,
//  cuts gather L1 wavefronts ~4x. Loads batched 8 rows deep (MLP 8).
//  Epilogue: aligned float4 LDS x2 + float4 __stcs (streaming store).

#define HH 224
#define WW 224
#define TT 32
#define NPLANES 768                     // B*C*T
#define TILE_Y 16
#define TILES_PER_PLANE (HH / TILE_Y)   // 14
#define THREADS 224
#define SCALE_F (14.0f / 15.0f)
#define FULLMASK 0xFFFFFFFFu

__global__ __launch_bounds__(THREADS) void shake_bilinear_shfl_kernel(
    const float* __restrict__ vid,
    const int*   __restrict__ sh,
    const int*   __restrict__ sw,
    float*       __restrict__ out)
{
    __shared__ float hrow[TILE_Y][WW];   // 14336 B

    int blk  = blockIdx.x;
    int tile = blk % TILES_PER_PLANE;
    int p    = blk / TILES_PER_PLANE;    // plane = (b*C + c)*T + t
    int t    = p & (TT - 1);
    int sht  = __ldg(sh + t);
    int swt  = __ldg(sw + t);
    int yb   = tile * TILE_Y;
    int tid  = threadIdx.x;

    // Base source row for this tile (may be -1 at the top edge).
    float sy0  = ((float)(yb + sht) + 0.5f) * SCALE_F - 0.5f;
    int   base = (int)floorf(sy0);

    const float* plane = vid + (long long)p * (HH * WW);

    // ---- Gather + horizontal lerp via warp shuffle ----
    {
        int   x    = tid;                // 0..223
        int   lane = tid & 31;
        int   wx0  = tid & ~31;          // first x of this warp's strip

        // Per-thread horizontal weights/taps
        float sx  = ((float)(x + swt) + 0.5f) * SCALE_F - 0.5f;
        float f0  = floorf(sx);
        float fx  = sx - f0;
        int   x0  = (int)f0;
        int   x0c = max(x0, 0);
        int   x1c = min(x0 + 1, WW - 1);

        // Warp source window base = x0 of the warp's first output column.
        float sxw   = ((float)(wx0 + swt) + 0.5f) * SCALE_F - 0.5f;
        int   baseX = (int)floorf(sxw);
        int   i0    = x0c - baseX;       // in [0,31]
        int   i1    = x1c - baseX;       // in [0,31]
        int   colL  = min(max(baseX + lane, 0), WW - 1);  // lane's source col

#pragma unroll
        for (int w = 0; w < 2; w++) {
            float v[8];
#pragma unroll
            for (int r8 = 0; r8 < 8; r8++) {
                int r    = w * 8 + r8;
                int srcr = min(max(base + r, 0), HH - 1);
                v[r8] = __ldg(plane + srcr * WW + colL);   // 1 coalesced LDG
            }
#pragma unroll
            for (int r8 = 0; r8 < 8; r8++) {
                float a = __shfl_sync(FULLMASK, v[r8], i0);
                float b = __shfl_sync(FULLMASK, v[r8], i1);
                hrow[w * 8 + r8][x] = fmaf(fx, b - a, a);
            }
        }
    }
    __syncthreads();

    // ---- Vertical lerp: aligned float4 LDS x2 + streaming float4 store ----
    int x4 = tid % (WW / 4);             // 0..55
    int yy = tid / (WW / 4);             // 0..3
    int xb = x4 * 4;

    float4* outp = (float4*)(out + (long long)p * (HH * WW));
#pragma unroll
    for (int k = 0; k < 4; k++) {
        int   y   = yy + 4 * k;          // 0..15
        float sy  = ((float)(yb + y + sht) + 0.5f) * SCALE_F - 0.5f;
        float f0  = floorf(sy);
        float fy  = sy - f0;
        int   r0  = (int)f0 - base;      // in [0,14]; r0+1 <= 15 (clamped rows)

        float4 a = *(const float4*)(&hrow[r0][xb]);
        float4 b = *(const float4*)(&hrow[r0 + 1][xb]);

        float4 res;
        res.x = fminf(fmaxf(fmaf(fy, b.x - a.x, a.x), 0.0f), 1.0f);
        res.y = fminf(fmaxf(fmaf(fy, b.y - a.y, a.y), 0.0f), 1.0f);
        res.z = fminf(fmaxf(fmaf(fy, b.z - a.z, a.z), 0.0f), 1.0f);
        res.w = fminf(fmaxf(fmaf(fy, b.w - a.w, a.w), 0.0f), 1.0f);

        __stcs(&outp[(yb + y) * (WW / 4) + x4], res);
    }
}

extern "C" void kernel_launch(void* const* d_in, const int* in_sizes, int n_in,
                              void* d_out, int out_size)
{
    const float* vid = (const float*)d_in[0];
    const int*   sh  = (const int*)d_in[1];
    const int*   sw  = (const int*)d_in[2];
    float*       out = (float*)d_out;

    int blocks = NPLANES * TILES_PER_PLANE; // 10752
    shake_bilinear_shfl_kernel<<<blocks, THREADS>>>(vid, sh, sw, out);
}